// round 1
// baseline (speedup 1.0000x reference)
#include <cuda_runtime.h>

#define B_   32
#define IN_  2048
#define DK   8      // Din
#define N_   64     // num output capsules
#define C_   32     // weight channels
#define DD   16     // Dout
#define IPC  (IN_/C_)   // 64 input capsules per channel

// scratch (device globals — no allocation allowed)
__device__ float g_X[B_*C_*DK];        // per-channel x sums (iter 0)
__device__ float g_U[B_*N_*C_*DK];     // accumulated out^T W  (gives logits via U.x)
__device__ float g_y[B_*N_*C_*DK];     // coef-weighted x sums

// ---------------------------------------------------------------------------
// Kernel 1: X[b,c,k] = sum_{j<64} x[b, c*64+j, k]
// grid 32 (one per b), 256 threads: thread t -> (c = t>>3, k = t&7)
// ---------------------------------------------------------------------------
__global__ void k_reduce_x(const float* __restrict__ x) {
    int b = blockIdx.x;
    int t = threadIdx.x;
    int c = t >> 3, k = t & 7;
    const float* xp = x + (size_t)(b*IN_ + c*IPC) * DK + k;
    float s = 0.f;
    #pragma unroll 8
    for (int j = 0; j < IPC; ++j) s += xp[j*DK];
    g_X[(b*C_ + c)*DK + k] = s;
}

// ---------------------------------------------------------------------------
// Kernel 2: per (b,n) warp:
//   s[d]  = yscale * sum_{c,k} W[n,c,d,k] * yv[b,n,c,k] + bias[n,d]
//   out   = squash(s)
//   mode 0: yv = X (n-independent), yscale = 1/64, U  = out^T W   (overwrite)
//   mode 1: yv = g_y,               yscale = 1,    U += out^T W
//   mode 2: yv = g_y,               write out to d_out, skip U
// 256 threads (8 warps). pair = blockIdx*8+w ; b = pair&31, n = pair>>5
// (warps in a CTA share n -> W[n] stays hot in L1)
// ---------------------------------------------------------------------------
__global__ void __launch_bounds__(256) k_s(const float* __restrict__ W,
                                           const float* __restrict__ bias,
                                           float* __restrict__ out,
                                           int mode) {
    int w = threadIdx.x >> 5;
    int l = threadIdx.x & 31;
    int pair = blockIdx.x * 8 + w;
    int b = pair & (B_-1);
    int n = pair >> 5;

    // ---- s-phase: lane l holds d = l>>1, k-quad = 4*(l&1)..+3 (float4 of W[n][c])
    const float4* Wc = (const float4*)(W + (size_t)n * C_ * DD * DK) + l;
    const float4* yp;
    float yscale;
    if (mode == 0) { yp = (const float4*)(g_X + b*C_*DK) + (l & 1);              yscale = 1.f/64.f; }
    else           { yp = (const float4*)(g_y + (size_t)((b*N_ + n)*C_)*DK) + (l & 1); yscale = 1.f; }

    float acc = 0.f;
    #pragma unroll 8
    for (int c = 0; c < C_; ++c) {
        float4 wv = Wc[c*32];     // W[n][c] is 128 floats = 32 float4, lane picks its own
        float4 yv = yp[c*2];      // y[b,n,c] is 8 floats = 2 float4
        acc += wv.x*yv.x + wv.y*yv.y + wv.z*yv.z + wv.w*yv.w;
    }
    // combine the two k-quads for each d (lanes l, l^1 share d)
    acc += __shfl_xor_sync(0xffffffffu, acc, 1);
    int d = l >> 1;
    float s = acc * yscale + bias[n*DD + d];

    // squash: sn = sum_d s_d^2 (each parity class of lanes holds each d once)
    float sq = s * s;
    #pragma unroll
    for (int off = 2; off < 32; off <<= 1) sq += __shfl_xor_sync(0xffffffffu, sq, off);
    float sn = sq;
    float scale = sn / (1.f + sn) * rsqrtf(sn + 1e-7f);
    float o = scale * s;          // out_d, duplicated on lanes 2d, 2d+1

    if (mode == 2) {
        if ((l & 1) == 0) out[(size_t)(b*N_ + n)*DD + d] = o;
        return;
    }

    // ---- U-phase: U[b,n,c,k] (+)= sum_d o_d * W[n,c,d,k]
    // scalar mapping: k = l&7, g = l>>3 ; lane covers d = g+4j via floats l+32j
    int g = l >> 3;
    float o0 = __shfl_sync(0xffffffffu, o, (g     ) * 2);
    float o1 = __shfl_sync(0xffffffffu, o, (g +  4) * 2);
    float o2 = __shfl_sync(0xffffffffu, o, (g +  8) * 2);
    float o3 = __shfl_sync(0xffffffffu, o, (g + 12) * 2);

    const float* Ws = W + (size_t)n * C_ * DD * DK + l;
    float* Up = g_U + (size_t)((b*N_ + n)*C_) * DK;
    #pragma unroll 8
    for (int c = 0; c < C_; ++c) {
        const float* wc = Ws + c * DD * DK;
        float u = o0*wc[0] + o1*wc[32] + o2*wc[64] + o3*wc[96];
        u += __shfl_xor_sync(0xffffffffu, u, 8);
        u += __shfl_xor_sync(0xffffffffu, u, 16);
        if (l < 8) {
            if (mode == 0) Up[c*DK + l]  = u;
            else           Up[c*DK + l] += u;
        }
    }
}

// ---------------------------------------------------------------------------
// Kernel 3: routing step. grid = B * (C/2), 128 threads (4 warps).
// Each CTA owns 2 channels; 2 warps per channel, 32 capsules (i) each.
// lane l handles n0=l and n1=l+32: logits = U.x, softmax over n (warp reduce),
// register-resident y accumulation, 2-warp combine through smem.
// ---------------------------------------------------------------------------
#define CH 2
__global__ void __launch_bounds__(128) k_route(const float* __restrict__ x) {
    __shared__ float xs[CH*IPC*DK];     // 1024 floats
    __shared__ float ybuf[CH*N_*DK];    // 1024 floats

    int blk = blockIdx.x;
    int b = blk >> 4;                   // 16 blocks per b (C/CH = 16)
    int cbase = (blk & 15) * CH;
    int t = threadIdx.x;

    // stage x for both channels: 1024 contiguous floats = 256 float4
    {
        const float4* xg = (const float4*)(x + (size_t)(b*IN_ + cbase*IPC) * DK);
        float4* xs4 = (float4*)xs;
        xs4[t]       = xg[t];
        xs4[t + 128] = xg[t + 128];
    }
    __syncthreads();

    int w = t >> 5, l = t & 31;
    int cl = w >> 1, hw = w & 1;
    int c = cbase + cl;

    // U rows for n0 = l, n1 = l+32 (8 floats each)
    const float4* Ub = (const float4*)g_U + (size_t)((b*N_)*C_ + c) * 2;
    float4 u0a = Ub[(size_t)l*64],        u0b = Ub[(size_t)l*64 + 1];
    float4 u1a = Ub[(size_t)(l+32)*64],   u1b = Ub[(size_t)(l+32)*64 + 1];

    float y0a=0,y0b=0,y0c=0,y0d=0,y0e=0,y0f=0,y0g=0,y0h=0;
    float y1a=0,y1b=0,y1c=0,y1d=0,y1e=0,y1f=0,y1g=0,y1h=0;

    const float4* xw = (const float4*)(xs + (cl*IPC + hw*32) * DK);
    #pragma unroll 4
    for (int i = 0; i < 32; ++i) {
        float4 xa = xw[i*2], xb = xw[i*2 + 1];
        float l0 = u0a.x*xa.x + u0a.y*xa.y + u0a.z*xa.z + u0a.w*xa.w
                 + u0b.x*xb.x + u0b.y*xb.y + u0b.z*xb.z + u0b.w*xb.w;
        float l1 = u1a.x*xa.x + u1a.y*xa.y + u1a.z*xa.z + u1a.w*xa.w
                 + u1b.x*xb.x + u1b.y*xb.y + u1b.z*xb.z + u1b.w*xb.w;
        // softmax over 64 n's (no max-sub: |logit| small by construction)
        float e0 = __expf(l0), e1 = __expf(l1);
        float ts = e0 + e1;
        #pragma unroll
        for (int off = 1; off < 32; off <<= 1) ts += __shfl_xor_sync(0xffffffffu, ts, off);
        float inv = __fdividef(1.f, ts);
        float c0 = e0 * inv, c1 = e1 * inv;
        y0a += c0*xa.x; y0b += c0*xa.y; y0c += c0*xa.z; y0d += c0*xa.w;
        y0e += c0*xb.x; y0f += c0*xb.y; y0g += c0*xb.z; y0h += c0*xb.w;
        y1a += c1*xa.x; y1b += c1*xa.y; y1c += c1*xa.z; y1d += c1*xa.w;
        y1e += c1*xb.x; y1f += c1*xb.y; y1g += c1*xb.z; y1h += c1*xb.w;
    }
    __syncthreads();

    float4* yb4 = (float4*)ybuf + cl * N_ * 2;
    if (hw == 0) {
        yb4[l*2]          = make_float4(y0a,y0b,y0c,y0d);
        yb4[l*2 + 1]      = make_float4(y0e,y0f,y0g,y0h);
        yb4[(l+32)*2]     = make_float4(y1a,y1b,y1c,y1d);
        yb4[(l+32)*2 + 1] = make_float4(y1e,y1f,y1g,y1h);
    }
    __syncthreads();
    if (hw == 1) {
        float4* yg = (float4*)g_y + (size_t)((b*N_)*C_ + c) * 2;
        float4 p;
        p = yb4[l*2];            yg[(size_t)l*64]        = make_float4(p.x+y0a, p.y+y0b, p.z+y0c, p.w+y0d);
        p = yb4[l*2 + 1];        yg[(size_t)l*64 + 1]    = make_float4(p.x+y0e, p.y+y0f, p.z+y0g, p.w+y0h);
        p = yb4[(l+32)*2];       yg[(size_t)(l+32)*64]   = make_float4(p.x+y1a, p.y+y1b, p.z+y1c, p.w+y1d);
        p = yb4[(l+32)*2 + 1];   yg[(size_t)(l+32)*64+1] = make_float4(p.x+y1e, p.y+y1f, p.z+y1g, p.w+y1h);
    }
}

// ---------------------------------------------------------------------------
extern "C" void kernel_launch(void* const* d_in, const int* in_sizes, int n_in,
                              void* d_out, int out_size) {
    const float* x    = (const float*)d_in[0];   // [32, 2048, 8]
    const float* W    = (const float*)d_in[1];   // [64, 32, 16, 8]
    const float* bias = (const float*)d_in[2];   // [64, 16]
    float* out = (float*)d_out;                  // [32, 64, 16]

    k_reduce_x<<<B_, 256>>>(x);
    k_s<<<(B_*N_)/8, 256>>>(W, bias, out, 0);    // iter 0: uniform coef, build U
    k_route<<<B_*(C_/CH), 128>>>(x);             // iter 1: softmax(U.x) -> y
    k_s<<<(B_*N_)/8, 256>>>(W, bias, out, 1);    // iter 1: s,out, U += ...
    k_route<<<B_*(C_/CH), 128>>>(x);             // iter 2: softmax(U.x) -> y
    k_s<<<(B_*N_)/8, 256>>>(W, bias, out, 2);    // iter 2: final output
}

// round 5
// speedup vs baseline: 1.0915x; 1.0915x over previous
#include <cuda_runtime.h>

#define B_   32
#define IN_  2048
#define DK   8      // Din
#define N_   64     // num output capsules
#define C_   32     // weight channels
#define DD   16     // Dout
#define IPC  (IN_/C_)   // 64 input capsules per channel
#define CH   2      // channels per route CTA
#define GRID 512
#define TPB  128

// scratch (device globals — no allocation allowed)
__device__ float g_X[B_*C_*DK];        // per-channel x sums (iter 0)
__device__ float g_U[B_*N_*C_*DK];     // accumulated out^T W  (logits via U.x)
__device__ float g_y[B_*N_*C_*DK];     // coef-weighted x sums

// grid barrier state. g_cnt returns to 0 after every barrier; g_gen is
// monotonically increasing (compared relatively) -> deterministic across
// graph replays, no reset needed.
__device__ unsigned g_cnt;
__device__ volatile unsigned g_gen;

__device__ __forceinline__ void grid_sync() {
    __syncthreads();
    if (threadIdx.x == 0) {
        unsigned gen = g_gen;
        __threadfence();   // (a) publish this CTA's writes, (b) order gen-read before atomic
        if (atomicAdd(&g_cnt, 1u) == GRID - 1u) {
            g_cnt = 0u;
            __threadfence();
            g_gen = gen + 1u;          // release
        } else {
            while (g_gen == gen) __nanosleep(32);
        }
    }
    __syncthreads();
}

// ---------------------------------------------------------------------------
// k_s phase: per (b,n) warp. pair = blockIdx*4 + warp; all 4 warps in a CTA
// share n -> W[n] (16KB) stays hot in L1 across the whole fused kernel.
//   s[d]  = yscale * sum_{c,k} W[n,c,d,k]*yv[b,n,c,k] + bias[n,d]; out=squash(s)
//   MODE 0: yv = X (n-independent), scale 1/64, U  = out^T W (overwrite)
//   MODE 1: yv = g_y, U += out^T W
//   MODE 2: yv = g_y, write final output, skip U
// ---------------------------------------------------------------------------
template<int MODE>
__device__ __forceinline__ void ks_phase(const float* __restrict__ W,
                                         const float* __restrict__ bias,
                                         float* __restrict__ out) {
    int t = threadIdx.x;
    int w = t >> 5, l = t & 31;
    int pair = blockIdx.x * 4 + w;
    int b = pair & (B_-1);
    int n = pair >> 5;

    // ---- s-phase: lane l holds d = l>>1, k-quad = 4*(l&1)..+3
    const float4* Wc = (const float4*)(W + (size_t)n * C_ * DD * DK) + l;
    float acc = 0.f;
    if (MODE == 0) {
        const float4* yp = (const float4*)(g_X + b*C_*DK) + (l & 1);
        #pragma unroll 8
        for (int c = 0; c < C_; ++c) {
            float4 wv = Wc[c*32];
            float4 yv = yp[c*2];
            acc += wv.x*yv.x + wv.y*yv.y + wv.z*yv.z + wv.w*yv.w;
        }
        acc *= (1.f/64.f);
    } else {
        // g_y was (re)written by other SMs this launch -> bypass L1
        const float4* yp = (const float4*)(g_y + (size_t)((b*N_ + n)*C_)*DK) + (l & 1);
        #pragma unroll 8
        for (int c = 0; c < C_; ++c) {
            float4 wv = Wc[c*32];
            float4 yv = __ldcg(yp + c*2);
            acc += wv.x*yv.x + wv.y*yv.y + wv.z*yv.z + wv.w*yv.w;
        }
    }
    acc += __shfl_xor_sync(0xffffffffu, acc, 1);   // combine two k-quads per d
    int d = l >> 1;
    float s = acc + bias[n*DD + d];

    // squash
    float sq = s * s;
    #pragma unroll
    for (int off = 2; off < 32; off <<= 1) sq += __shfl_xor_sync(0xffffffffu, sq, off);
    float scale = sq / (1.f + sq) * rsqrtf(sq + 1e-7f);
    float o = scale * s;            // out_d on lanes 2d, 2d+1

    if (MODE == 2) {
        if ((l & 1) == 0) out[(size_t)(b*N_ + n)*DD + d] = o;
        return;                     // last phase: no barrier after, divergence OK
    }

    // ---- U-phase: U[b,n,c,k] (+)= sum_d o_d * W[n,c,d,k]
    // k = l&7, g = l>>3 ; lane covers d = g+4j via floats l+32j (coalesced 128B)
    int g = l >> 3;
    float o0 = __shfl_sync(0xffffffffu, o, (g     ) * 2);
    float o1 = __shfl_sync(0xffffffffu, o, (g +  4) * 2);
    float o2 = __shfl_sync(0xffffffffu, o, (g +  8) * 2);
    float o3 = __shfl_sync(0xffffffffu, o, (g + 12) * 2);

    const float* Ws = W + (size_t)n * C_ * DD * DK + l;
    float* Up = g_U + (size_t)((b*N_ + n)*C_) * DK;
    #pragma unroll 8
    for (int c = 0; c < C_; ++c) {
        const float* wc = Ws + c * DD * DK;
        float u = o0*wc[0] + o1*wc[32] + o2*wc[64] + o3*wc[96];
        u += __shfl_xor_sync(0xffffffffu, u, 8);
        u += __shfl_xor_sync(0xffffffffu, u, 16);
        if (l < 8) {
            if (MODE == 0) Up[c*DK + l] = u;
            else           Up[c*DK + l] = u + __ldcg(Up + c*DK + l); // own warp's line, ldcg for safety
        }
    }
}

// ---------------------------------------------------------------------------
// route phase: CTA owns 2 channels; 2 warps per channel, 32 capsules each.
// lane l handles n0=l, n1=l+32: logits=U.x, softmax over 64 n (warp reduce),
// register-resident y accumulation, 2-warp combine through smem.
// x tile staged to smem once (first call) and reused on the second call.
// ---------------------------------------------------------------------------
__device__ __forceinline__ void route_phase(const float* __restrict__ x,
                                            float* xs, float* ybuf, bool stage) {
    int t = threadIdx.x;
    int blk = blockIdx.x;
    int b = blk >> 4;                   // 16 blocks per b (C/CH)
    int cbase = (blk & 15) * CH;

    if (stage) {
        const float4* xg = (const float4*)(x + (size_t)(b*IN_ + cbase*IPC) * DK);
        float4* xs4 = (float4*)xs;
        xs4[t]       = xg[t];
        xs4[t + 128] = xg[t + 128];
    }
    __syncthreads();

    int w = t >> 5, l = t & 31;
    int cl = w >> 1, hw = w & 1;
    int c = cbase + cl;

    // U rows for n0=l, n1=l+32 (written by other SMs this launch -> ldcg)
    const float4* Ub = (const float4*)g_U + (size_t)((b*N_)*C_ + c) * 2;
    float4 u0a = __ldcg(Ub + (size_t)l*64),      u0b = __ldcg(Ub + (size_t)l*64 + 1);
    float4 u1a = __ldcg(Ub + (size_t)(l+32)*64), u1b = __ldcg(Ub + (size_t)(l+32)*64 + 1);

    float y0a=0,y0b=0,y0c=0,y0d=0,y0e=0,y0f=0,y0g=0,y0h=0;
    float y1a=0,y1b=0,y1c=0,y1d=0,y1e=0,y1f=0,y1g=0,y1h=0;

    const float4* xw = (const float4*)(xs + (cl*IPC + hw*32) * DK);
    #pragma unroll 4
    for (int i = 0; i < 32; ++i) {
        float4 xa = xw[i*2], xb = xw[i*2 + 1];
        float l0 = u0a.x*xa.x + u0a.y*xa.y + u0a.z*xa.z + u0a.w*xa.w
                 + u0b.x*xb.x + u0b.y*xb.y + u0b.z*xb.z + u0b.w*xb.w;
        float l1 = u1a.x*xa.x + u1a.y*xa.y + u1a.z*xa.z + u1a.w*xa.w
                 + u1b.x*xb.x + u1b.y*xb.y + u1b.z*xb.z + u1b.w*xb.w;
        float e0 = __expf(l0), e1 = __expf(l1);   // |logit| small: no max-sub needed
        float ts = e0 + e1;
        #pragma unroll
        for (int off = 1; off < 32; off <<= 1) ts += __shfl_xor_sync(0xffffffffu, ts, off);
        float inv = __fdividef(1.f, ts);
        float c0 = e0 * inv, c1 = e1 * inv;
        y0a += c0*xa.x; y0b += c0*xa.y; y0c += c0*xa.z; y0d += c0*xa.w;
        y0e += c0*xb.x; y0f += c0*xb.y; y0g += c0*xb.z; y0h += c0*xb.w;
        y1a += c1*xa.x; y1b += c1*xa.y; y1c += c1*xa.z; y1d += c1*xa.w;
        y1e += c1*xb.x; y1f += c1*xb.y; y1g += c1*xb.z; y1h += c1*xb.w;
    }
    __syncthreads();

    float4* yb4 = (float4*)ybuf + cl * N_ * 2;
    if (hw == 0) {
        yb4[l*2]          = make_float4(y0a,y0b,y0c,y0d);
        yb4[l*2 + 1]      = make_float4(y0e,y0f,y0g,y0h);
        yb4[(l+32)*2]     = make_float4(y1a,y1b,y1c,y1d);
        yb4[(l+32)*2 + 1] = make_float4(y1e,y1f,y1g,y1h);
    }
    __syncthreads();
    if (hw == 1) {
        float4* yg = (float4*)g_y + (size_t)((b*N_)*C_ + c) * 2;
        float4 p;
        p = yb4[l*2];            yg[(size_t)l*64]        = make_float4(p.x+y0a, p.y+y0b, p.z+y0c, p.w+y0d);
        p = yb4[l*2 + 1];        yg[(size_t)l*64 + 1]    = make_float4(p.x+y0e, p.y+y0f, p.z+y0g, p.w+y0h);
        p = yb4[(l+32)*2];       yg[(size_t)(l+32)*64]   = make_float4(p.x+y1a, p.y+y1b, p.z+y1c, p.w+y1d);
        p = yb4[(l+32)*2 + 1];   yg[(size_t)(l+32)*64+1] = make_float4(p.x+y1e, p.y+y1f, p.z+y1g, p.w+y1h);
    }
}

// ---------------------------------------------------------------------------
// One fused persistent kernel: grid 512 x 128 (single wave, guaranteed
// co-resident: <=85 regs via launch_bounds, 8.5KB smem -> >=6 CTAs/SM >> 4 needed)
// ---------------------------------------------------------------------------
__global__ void __launch_bounds__(TPB, 6) fused_kernel(
        const float* __restrict__ x, const float* __restrict__ W,
        const float* __restrict__ bias, float* __restrict__ out) {
    __shared__ float xs[CH*IPC*DK];     // 4KB: x tile, staged once, reused
    __shared__ float ybuf[CH*N_*DK];    // 4KB: cross-warp y combine

    // Phase 1: X[b,c,k] = sum_{j<64} x[b, c*64+j, k]   (8192 elements)
    {
        int gt = blockIdx.x * TPB + threadIdx.x;
        if (gt < B_*C_*DK) {
            int b = gt >> 8;           // C_*DK = 256 per b
            int ck = gt & 255;
            const float* xp = x + (size_t)b*IN_*DK + (ck >> 3)*IPC*DK + (ck & 7);
            float s = 0.f;
            #pragma unroll 16
            for (int j = 0; j < IPC; ++j) s += xp[j*DK];
            g_X[gt] = s;
        }
    }
    grid_sync();
    ks_phase<0>(W, bias, out);          // iter 0: uniform coef, build U
    grid_sync();
    route_phase(x, xs, ybuf, true);     // iter 1: softmax(U.x) -> y
    grid_sync();
    ks_phase<1>(W, bias, out);          // iter 1: s,out, U += ...
    grid_sync();
    route_phase(x, xs, ybuf, false);    // iter 2 (x tile already in smem)
    grid_sync();
    ks_phase<2>(W, bias, out);          // iter 2: final output
}

// ---------------------------------------------------------------------------
extern "C" void kernel_launch(void* const* d_in, const int* in_sizes, int n_in,
                              void* d_out, int out_size) {
    const float* x    = (const float*)d_in[0];   // [32, 2048, 8]
    const float* W    = (const float*)d_in[1];   // [64, 32, 16, 8]
    const float* bias = (const float*)d_in[2];   // [64, 16]
    float* out = (float*)d_out;                  // [32, 64, 16]

    fused_kernel<<<GRID, TPB>>>(x, W, bias, out);
}